// round 7
// baseline (speedup 1.0000x reference)
#include <cuda_runtime.h>
#include <math.h>

#define Bdim 4
#define Ndim 48
#define Rdim 16
#define Tdim 33
#define NCdim 80
#define NIdim 5
#define NN (Ndim * Ndim)          // 2304
#define NEGV -1000.0f
#define PR 36                     // prep rows per CTA
#define NTHREADS 288
#define NBLOCKS (NCdim * Bdim)    // 320

// g_M[b,t][u*48+v] = trans[b,u,v,t]
__device__ float g_M[Bdim * Tdim * NN];
// scratch: exp(path score) per [b, c, xy]
__device__ float g_scratch[Bdim * NCdim * NN];

// ---- sense-reversing grid barrier (all CTAs co-resident by construction) ----
__device__ unsigned g_bar_count = 0;
__device__ unsigned g_bar_gen   = 0;

__device__ __forceinline__ void grid_barrier(unsigned nb)
{
    __syncthreads();
    if (threadIdx.x == 0) {
        __threadfence();
        const unsigned gen = *(volatile unsigned*)&g_bar_gen;
        if (atomicAdd(&g_bar_count, 1u) == nb - 1u) {
            g_bar_count = 0;                 // all arrived; safe to reset
            __threadfence();
            *(volatile unsigned*)&g_bar_gen = gen + 1u;
        } else {
            while (*(volatile unsigned*)&g_bar_gen == gen) {}
        }
        __threadfence();
    }
    __syncthreads();
}

__global__ __launch_bounds__(NTHREADS, 4)
void fused_kernel(const float* __restrict__ trans,
                  const int*   __restrict__ rules,
                  const int*   __restrict__ type_mask,
                  const float* __restrict__ weights,
                  const float* __restrict__ biases,
                  float*       __restrict__ out)
{
    __shared__ float P[NN];                    // prep tile / hop0^T / hop2
    __shared__ float Q[NN];                    // hop1 / S^T
    __shared__ float Tpad[Ndim * (Ndim + 1)];  // hop0 row-major, padded 49

    const int tid = threadIdx.x;
    const int pid = blockIdx.x;

    // ============ phase 1: transpose [B*2304, 33] -> g_M ============
    if (pid < (Bdim * NN) / PR) {              // 256 active CTAs
        const int b     = pid >> 6;
        const int chunk = pid & 63;
        const int row0  = chunk * PR;

        const float* src = trans + ((size_t)b * NN + row0) * Tdim;
        for (int i = tid; i < PR * Tdim; i += NTHREADS)
            P[i] = __ldg(src + i);             // fully coalesced
        __syncthreads();

        float* dst = g_M + (size_t)b * Tdim * NN + row0;
        for (int i = tid; i < PR * Tdim; i += NTHREADS) {
            const int t = i / PR;
            const int r = i - t * PR;
            dst[(size_t)t * NN + r] = P[r * Tdim + t];   // stride-33 smem: conflict-free
        }
    }
    grid_barrier(NBLOCKS);

    // ============ phase 2: max-plus DP, one CTA per (c,b) ============
    {
        const int c = pid % NCdim;
        const int b = pid / NCdim;

        const int tx  = tid % 12;              // col unit (4 wide)
        const int tyy = tid / 12;              // row unit (2 tall), 0..23
        const int col0 = tx * 4;
        const int row0 = tyy * 2;

        const int r0 = rules[c * 3 + 0];
        const int r1 = rules[c * 3 + 1];
        const int r2 = rules[c * 3 + 2];

        const float4* h0 = (const float4*)(g_M + (size_t)(b * Tdim + r0) * NN);
        const float4* h1 = (const float4*)(g_M + (size_t)(b * Tdim + r1) * NN);
        const float4* h2 = (const float4*)(g_M + (size_t)(b * Tdim + r2) * NN);

        float4* P4 = (float4*)P;
        float4* Q4 = (float4*)Q;
        float2* P2 = (float2*)P;
        float2* Q2 = (float2*)Q;

        // load hop0 -> padded tile, hop1 -> Q   (576 float4s, 2/thread)
        #pragma unroll
        for (int j = 0; j < 2; j++) {
            const int fi = tid + j * NTHREADS;
            const float4 v0 = h0[fi];
            Q4[fi] = h1[fi];
            const int flat = fi * 4;
            const int u = flat / Ndim;
            const int v = flat - u * Ndim;
            float* tp = &Tpad[u * (Ndim + 1) + v];
            tp[0] = v0.x; tp[1] = v0.y; tp[2] = v0.z; tp[3] = v0.w;
        }
        __syncthreads();

        // P = hop0^T
        #pragma unroll
        for (int j = 0; j < 2; j++) {
            const int fi = tid + j * NTHREADS;
            const int flat = fi * 4;
            const int u = flat / Ndim;
            const int v = flat - u * Ndim;
            P4[fi] = make_float4(Tpad[(v + 0) * (Ndim + 1) + u],
                                 Tpad[(v + 1) * (Ndim + 1) + u],
                                 Tpad[(v + 2) * (Ndim + 1) + u],
                                 Tpad[(v + 3) * (Ndim + 1) + u]);
        }
        __syncthreads();

        float a00=-INFINITY,a01=-INFINITY,a02=-INFINITY,a03=-INFINITY;
        float a10=-INFINITY,a11=-INFINITY,a12=-INFINITY,a13=-INFINITY;

        // ---- stage 1: S = hop0 (max-plus) hop1 ----
        #pragma unroll 8
        for (int k = 0; k < Ndim; k++) {
            const float2 av = P2[k * 24 + tyy];   // hop0^T[k][row0..+1]
            const float4 bv = Q4[k * 12 + tx];    // hop1[k][col0..+3]
            a00=fmaxf(a00,av.x+bv.x); a01=fmaxf(a01,av.x+bv.y); a02=fmaxf(a02,av.x+bv.z); a03=fmaxf(a03,av.x+bv.w);
            a10=fmaxf(a10,av.y+bv.x); a11=fmaxf(a11,av.y+bv.y); a12=fmaxf(a12,av.y+bv.z); a13=fmaxf(a13,av.y+bv.w);
        }
        __syncthreads();   // all reads of P,Q done

        // write S^T into Q: Q[c*48 + r]; reload P with hop2 (row-major)
        {
            float2* qst = (float2*)(Q + col0 * Ndim + row0);
            qst[0 * 24] = make_float2(a00, a10);
            qst[1 * 24] = make_float2(a01, a11);
            qst[2 * 24] = make_float2(a02, a12);
            qst[3 * 24] = make_float2(a03, a13);
        }
        #pragma unroll
        for (int j = 0; j < 2; j++)
            P4[tid + j * NTHREADS] = h2[tid + j * NTHREADS];
        __syncthreads();

        // ---- stage 2: out = exp( S (max-plus) hop2 ) ----
        a00=-INFINITY;a01=-INFINITY;a02=-INFINITY;a03=-INFINITY;
        a10=-INFINITY;a11=-INFINITY;a12=-INFINITY;a13=-INFINITY;

        #pragma unroll 8
        for (int k = 0; k < Ndim; k++) {
            const float2 av = Q2[k * 24 + tyy];   // S^T[k][row0..+1]
            const float4 bv = P4[k * 12 + tx];    // hop2[k][col0..+3]
            a00=fmaxf(a00,av.x+bv.x); a01=fmaxf(a01,av.x+bv.y); a02=fmaxf(a02,av.x+bv.z); a03=fmaxf(a03,av.x+bv.w);
            a10=fmaxf(a10,av.y+bv.x); a11=fmaxf(a11,av.y+bv.y); a12=fmaxf(a12,av.y+bv.z); a13=fmaxf(a13,av.y+bv.w);
        }

        float* outp = g_scratch + ((size_t)b * NCdim + c) * NN;
        *(float4*)(outp + (row0 + 0) * Ndim + col0) = make_float4(__expf(a00), __expf(a01), __expf(a02), __expf(a03));
        *(float4*)(outp + (row0 + 1) * Ndim + col0) = make_float4(__expf(a10), __expf(a11), __expf(a12), __expf(a13));
    }
    grid_barrier(NBLOCKS);

    // ============ phase 3: combine + mask ============
    {
        const int gid = pid * NTHREADS + tid;       // 0 .. 92159
        if (gid < Bdim * NN * 4) {
            const int g   = gid & 3;                // triple group of 4
            const int bxy = gid >> 2;
            const int xy  = bxy % NN;
            const int b   = bxy / NN;

            const float* wp = weights + g * 20;
            const float* bp = biases  + g * 4;

            float acc0 = __ldg(bp + 0);
            float acc1 = __ldg(bp + 1);
            float acc2 = __ldg(bp + 2);
            float acc3 = __ldg(bp + 3);

            const float* sp = g_scratch + ((size_t)b * NCdim + g * 20) * NN + xy;
            #pragma unroll
            for (int j = 0; j < 5; j++) {
                acc0 = fmaf(sp[(j +  0) * NN], __ldg(wp + j +  0), acc0);
                acc1 = fmaf(sp[(j +  5) * NN], __ldg(wp + j +  5), acc1);
                acc2 = fmaf(sp[(j + 10) * NN], __ldg(wp + j + 10), acc2);
                acc3 = fmaf(sp[(j + 15) * NN], __ldg(wp + j + 15), acc3);
            }

            const int4 m = *(const int4*)(type_mask + (size_t)bxy * Rdim + g * 4);
            float4 o;
            o.x = (m.x == 0) ? acc0 : NEGV;
            o.y = (m.y == 0) ? acc1 : NEGV;
            o.z = (m.z == 0) ? acc2 : NEGV;
            o.w = (m.w == 0) ? acc3 : NEGV;
            *(float4*)(out + (size_t)bxy * Rdim + g * 4) = o;
        }
    }
}

extern "C" void kernel_launch(void* const* d_in, const int* in_sizes, int n_in,
                              void* d_out, int out_size)
{
    const float* transitions = (const float*)d_in[0];
    const int*   type_mask   = (const int*)  d_in[1];
    const int*   rules       = (const int*)  d_in[2];
    const float* weights     = (const float*)d_in[3];
    const float* biases      = (const float*)d_in[4];
    float* out = (float*)d_out;

    fused_kernel<<<NBLOCKS, NTHREADS>>>(transitions, rules, type_mask,
                                        weights, biases, out);
}